// round 10
// baseline (speedup 1.0000x reference)
#include <cuda_runtime.h>
#include <cuda_bf16.h>

#define HW 200704
#define C 192
#define NH 6
#define D 32
#define PXS 100    // u32 stride for px-major bf16x2 tiles
#define WST 200    // u32 stride per k-pair row in weight chunk
#define WBUF 3200  // u32 per weight chunk buffer
#define MS  (96 * 192)   // u32 per packed weight matrix

#define TPA 64     // k12 tile px
#define QSA 72     // bf16 stride for ch-major xn tile
#define TPB 128    // k4 tile px

// ---------------- scratch ----------------------------------------------------
__device__ float    g_wcomp[3 * 36864];   // composed fp32 Wq',Wk',Wv'
__device__ float    g_bcomp[3 * 192];     // composed biases bq,bk,bv
__device__ unsigned g_wbf[2 * MS];        // packed bf16x2: [0]=Wv' [1]=proj
__device__ unsigned g_v[(size_t)HW * 96]; // v, px-major bf16x2
__device__ float    g_S[36864];           // Sigma xn xn^T (upper tiles valid)
__device__ float    g_m[192];             // Sigma xn
__device__ float    g_Gt[6 * 1024];       // A S B^T per head
__device__ float    g_qsA[192], g_ksB[192], g_Am[192], g_Bm[192];
__device__ unsigned g_gmbf[192 * 16];     // gm bf16x2 pairs [ch][e/2]

// ---------------- helpers ----------------------------------------------------
__device__ __forceinline__ unsigned packbf(float a, float b) {
    __nv_bfloat162 p = __floats2bfloat162_rn(a, b);
    return *(unsigned*)&p;
}
__device__ __forceinline__ float2 unpbf(unsigned u) {
    __nv_bfloat162 p = *(__nv_bfloat162*)&u;
    return __bfloat1622float2(p);
}
__device__ __forceinline__ void mma_bf16(float d[4], const unsigned a[4],
                                         unsigned b0, unsigned b1) {
    asm volatile(
        "mma.sync.aligned.m16n8k16.row.col.f32.bf16.bf16.f32 "
        "{%0,%1,%2,%3},{%4,%5,%6,%7},{%8,%9},{%0,%1,%2,%3};\n"
        : "+f"(d[0]), "+f"(d[1]), "+f"(d[2]), "+f"(d[3])
        : "r"(a[0]), "r"(a[1]), "r"(a[2]), "r"(a[3]), "r"(b0), "r"(b1));
}

__device__ __forceinline__ void wchunk_prefetch(unsigned* wbuf,
                                                const unsigned* __restrict__ wg,
                                                int ch, int tid) {
#pragma unroll
    for (int r = 0; r < 3; r++) {
        int seg = tid + r * 256;
        int j = seg / 48, off = (seg - j * 48) * 4;
        unsigned ds = (unsigned)__cvta_generic_to_shared(wbuf + j * WST + off);
        asm volatile("cp.async.cg.shared.global [%0], [%1], 16;"
                     :: "r"(ds), "l"(wg + ch * 3072 + j * 192 + off));
    }
    asm volatile("cp.async.commit_group;" ::: "memory");
}

// 64px-tile GEMM, warp grid 2Mx4N (warp tile 32px x 48ch)
__device__ __forceinline__ void gemm_db64(const unsigned* a_s, unsigned* w_s,
                                          const unsigned* __restrict__ wg,
                                          float acc[2][6][4], int tid) {
    const int lane = tid & 31, warp = tid >> 5;
    const int gid = lane >> 2, tg = lane & 3;
    const int mb = (warp & 1) * 32, nb = (warp >> 1) * 48;
    wchunk_prefetch(w_s, wg, 0, tid);
    for (int ch = 0; ch < 6; ch++) {
        asm volatile("cp.async.wait_group 0;" ::: "memory");
        __syncthreads();
        if (ch < 5) wchunk_prefetch(w_s + ((ch + 1) & 1) * WBUF, wg, ch + 1, tid);
        const unsigned* wb_base = w_s + (ch & 1) * WBUF;
#pragma unroll
        for (int kl = 0; kl < 2; kl++) {
            const int k2 = ch * 16 + kl * 8;
            unsigned a[2][4];
#pragma unroll
            for (int mt = 0; mt < 2; mt++) {
                const unsigned* ab = a_s + (mb + mt * 16 + gid) * PXS + k2 + tg;
                a[mt][0] = ab[0];
                a[mt][1] = ab[8 * PXS];
                a[mt][2] = ab[4];
                a[mt][3] = ab[8 * PXS + 4];
            }
#pragma unroll
            for (int nt = 0; nt < 6; nt++) {
                const unsigned* wb = wb_base + (kl * 8 + tg) * WST + nb + nt * 8 + gid;
                unsigned b0 = wb[0], b1 = wb[4 * WST];
#pragma unroll
                for (int mt = 0; mt < 2; mt++) mma_bf16(acc[mt][nt], a[mt], b0, b1);
            }
        }
    }
}

// 128px-tile GEMM, warp grid 2Mx4N (warp tile 64px x 48ch)
__device__ __forceinline__ void gemm_db128(const unsigned* a_s, unsigned* w_s,
                                           const unsigned* __restrict__ wg,
                                           float acc[4][6][4], int tid) {
    const int lane = tid & 31, warp = tid >> 5;
    const int gid = lane >> 2, tg = lane & 3;
    const int mb = (warp & 1) * 64, nb = (warp >> 1) * 48;
    wchunk_prefetch(w_s, wg, 0, tid);
    for (int ch = 0; ch < 6; ch++) {
        asm volatile("cp.async.wait_group 0;" ::: "memory");
        __syncthreads();
        if (ch < 5) wchunk_prefetch(w_s + ((ch + 1) & 1) * WBUF, wg, ch + 1, tid);
        const unsigned* wb_base = w_s + (ch & 1) * WBUF;
#pragma unroll
        for (int kl = 0; kl < 2; kl++) {
            const int k2 = ch * 16 + kl * 8;
            unsigned a[4][4];
#pragma unroll
            for (int mt = 0; mt < 4; mt++) {
                const unsigned* ab = a_s + (mb + mt * 16 + gid) * PXS + k2 + tg;
                a[mt][0] = ab[0];
                a[mt][1] = ab[8 * PXS];
                a[mt][2] = ab[4];
                a[mt][3] = ab[8 * PXS + 4];
            }
#pragma unroll
            for (int nt = 0; nt < 6; nt++) {
                const unsigned* wb = wb_base + (kl * 8 + tg) * WST + nb + nt * 8 + gid;
                unsigned b0 = wb[0], b1 = wb[4 * WST];
#pragma unroll
                for (int mt = 0; mt < 4; mt++) mma_bf16(acc[mt][nt], a[mt], b0, b1);
            }
        }
    }
}

// ---------------- prep_compose: W' = Wsel * W_pre, b' = Wsel * pre_b ---------
__global__ void prep_compose(const float* __restrict__ qkv_w,
                             const float* __restrict__ pre_w,
                             const float* __restrict__ pre_b) {
    int idx = blockIdx.x * 256 + threadIdx.x;
    if (idx < 110592) {
        int sel = idx / 36864, r = idx - sel * 36864;
        int o = r / 192, c = r - o * 192;
        const float* wr = qkv_w + (sel * 192 + o) * 192;
        float s = 0.f;
#pragma unroll 4
        for (int i = 0; i < 192; i++) s += __ldg(&wr[i]) * __ldg(&pre_w[i * 192 + c]);
        g_wcomp[idx] = s;
    } else if (idx < 111168) {
        int b = idx - 110592;
        int sel = b / 192, o = b - sel * 192;
        const float* wr = qkv_w + (sel * 192 + o) * 192;
        float s = 0.f;
        for (int i = 0; i < 192; i++) s += __ldg(&wr[i]) * __ldg(&pre_b[i]);
        g_bcomp[b] = s;
    }
}

// ---------------- prep_pack: pack Wv'+proj bf16x2, zero S/m ------------------
__global__ void prep_pack(const float* __restrict__ proj_w) {
    int idx = blockIdx.x * 256 + threadIdx.x;
    if (idx < 18432) {
        int cp = idx / 192, o = idx - cp * 192;
        const float* W = g_wcomp + 2 * 36864;
        g_wbf[idx] = packbf(W[o * 192 + 2 * cp], W[o * 192 + 2 * cp + 1]);
    } else if (idx < 36864) {
        int r = idx - 18432;
        int cp = r / 192, o = r - cp * 192;
        g_wbf[idx] = packbf(proj_w[o * 192 + 2 * cp], proj_w[o * 192 + 2 * cp + 1]);
    } else if (idx < 73728) {
        g_S[idx - 36864] = 0.f;
    } else if (idx < 73920) {
        g_m[idx - 73728] = 0.f;
    }
}

// ---------------- k12: LN + v GEMM + S/m accumulation ------------------------
__global__ __launch_bounds__(256, 2) void k12(const float* __restrict__ x,
                                              const float* __restrict__ lng,
                                              const float* __restrict__ lnb) {
    extern __shared__ unsigned sm[];
    unsigned* bufA = sm;                    // 6400: xn px-major bf16x2
    unsigned* xt   = sm + 6400;             // 6912: xn ch-major bf16 [192][72]
    unsigned* w_s  = sm + 13312;            // 6400: weight double buffer
    float* gb = (float*)(sm + 19712);       // 384: ln gamma/beta
    float* mu = gb + 384;                   // 64
    float* rs = mu + 64;                    // 64
    __nv_bfloat16* xt16 = (__nv_bfloat16*)xt;
    const int tid = threadIdx.x, lane = tid & 31, warp = tid >> 5;
    const int gid = lane >> 2, tg = lane & 3;
    const int mb = (warp & 1) * 32, nb = (warp >> 1) * 48;
    const int p0 = blockIdx.x * TPA;

    for (int i = tid; i < C; i += 256) {
        gb[i]       = lng[i];
        gb[192 + i] = lnb[i];
    }
    // x transpose into px-major bf16x2
    for (int c2 = warp; c2 < 96; c2 += 8) {
        int c = 2 * c2;
#pragma unroll
        for (int pb = 0; pb < TPA; pb += 32) {
            float v0 = x[(size_t)c * HW + p0 + pb + lane];
            float v1 = x[(size_t)(c + 1) * HW + p0 + pb + lane];
            bufA[(pb + lane) * PXS + c2] = packbf(v0, v1);
        }
    }
    __syncthreads();
    // LN stats
    for (int px = warp; px < TPA; px += 8) {
        float s = 0.f, s2 = 0.f;
        for (int c2 = lane; c2 < 96; c2 += 32) {
            float2 f = unpbf(bufA[px * PXS + c2]);
            s += f.x + f.y;
            s2 += f.x * f.x + f.y * f.y;
        }
#pragma unroll
        for (int o = 16; o; o >>= 1) {
            s  += __shfl_xor_sync(~0u, s, o);
            s2 += __shfl_xor_sync(~0u, s2, o);
        }
        if (lane == 0) {
            float m = s * (1.f / C), v = s2 * (1.f / C) - m * m;
            mu[px] = m;
            rs[px] = rsqrtf(v + 1e-5f);
        }
    }
    __syncthreads();
    // apply LN -> bufA (px-major) AND xt (ch-major)
    for (int px = warp; px < TPA; px += 8) {
        float m = mu[px], r = rs[px];
        for (int c2 = lane; c2 < 96; c2 += 32) {
            float2 f = unpbf(bufA[px * PXS + c2]);
            f.x = (f.x - m) * r * gb[2 * c2]     + gb[192 + 2 * c2];
            f.y = (f.y - m) * r * gb[2 * c2 + 1] + gb[192 + 2 * c2 + 1];
            unsigned pk = packbf(f.x, f.y);
            bufA[px * PXS + c2] = pk;
            __nv_bfloat162 pp = *(__nv_bfloat162*)&pk;
            xt16[(2 * c2) * QSA + px]     = pp.x;
            xt16[(2 * c2 + 1) * QSA + px] = pp.y;
        }
    }

    // ---- v GEMM (bias = composed bv) ----
    float acc[2][6][4];
#pragma unroll
    for (int nt = 0; nt < 6; nt++) {
        int o = nb + nt * 8 + 2 * tg;
        float b0 = __ldg(&g_bcomp[384 + o]), b1 = __ldg(&g_bcomp[384 + o + 1]);
#pragma unroll
        for (int mt = 0; mt < 2; mt++) {
            acc[mt][nt][0] = b0; acc[mt][nt][1] = b1;
            acc[mt][nt][2] = b0; acc[mt][nt][3] = b1;
        }
    }
    gemm_db64(bufA, w_s, g_wbf, acc, tid);
#pragma unroll
    for (int mt = 0; mt < 2; mt++)
#pragma unroll
        for (int nt = 0; nt < 6; nt++) {
            int px = mb + mt * 16 + gid, cp = (nb + nt * 8) / 2 + tg;
            g_v[(size_t)(p0 + px) * 96 + cp]     = packbf(acc[mt][nt][0], acc[mt][nt][1]);
            g_v[(size_t)(p0 + px + 8) * 96 + cp] = packbf(acc[mt][nt][2], acc[mt][nt][3]);
        }

    // ---- S accumulation: 21 upper 32x32 tiles via bf16 mma + fp32 RED ------
    // (xt visibility across threads guaranteed by gemm's internal barriers)
    for (int t = warp; t < 21; t += 8) {
        int i, j;
        if      (t < 6)  { i = 0; j = t; }
        else if (t < 11) { i = 1; j = t - 5; }
        else if (t < 15) { i = 2; j = t - 9; }
        else if (t < 18) { i = 3; j = t - 12; }
        else if (t < 20) { i = 4; j = t - 14; }
        else             { i = 5; j = 5; }
        float a2[2][4][4];
#pragma unroll
        for (int mt = 0; mt < 2; mt++)
#pragma unroll
            for (int nt = 0; nt < 4; nt++)
#pragma unroll
                for (int r = 0; r < 4; r++) a2[mt][nt][r] = 0.f;
#pragma unroll
        for (int kc = 0; kc < TPA; kc += 16) {
            unsigned a[2][4];
#pragma unroll
            for (int mt = 0; mt < 2; mt++) {
                const __nv_bfloat16* ab = xt16 + (i * 32 + mt * 16 + gid) * QSA + kc + 2 * tg;
                a[mt][0] = *(const unsigned*)(ab);
                a[mt][1] = *(const unsigned*)(ab + 8 * QSA);
                a[mt][2] = *(const unsigned*)(ab + 8);
                a[mt][3] = *(const unsigned*)(ab + 8 * QSA + 8);
            }
#pragma unroll
            for (int nt = 0; nt < 4; nt++) {
                const __nv_bfloat16* bb = xt16 + (j * 32 + nt * 8 + gid) * QSA + kc + 2 * tg;
                unsigned b0 = *(const unsigned*)(bb);
                unsigned b1 = *(const unsigned*)(bb + 8);
#pragma unroll
                for (int mt = 0; mt < 2; mt++) mma_bf16(a2[mt][nt], a[mt], b0, b1);
            }
        }
#pragma unroll
        for (int mt = 0; mt < 2; mt++)
#pragma unroll
            for (int nt = 0; nt < 4; nt++) {
                int r0 = i * 32 + mt * 16 + gid, c0 = j * 32 + nt * 8 + 2 * tg;
                atomicAdd(&g_S[r0 * 192 + c0],           a2[mt][nt][0]);
                atomicAdd(&g_S[r0 * 192 + c0 + 1],       a2[mt][nt][1]);
                atomicAdd(&g_S[(r0 + 8) * 192 + c0],     a2[mt][nt][2]);
                atomicAdd(&g_S[(r0 + 8) * 192 + c0 + 1], a2[mt][nt][3]);
            }
    }
    // ---- m accumulation ----
    if (tid < 192) {
        const unsigned* rp = xt + tid * (QSA / 2);
        float s = 0.f;
#pragma unroll
        for (int p = 0; p < TPA / 2; p++) {
            float2 f = unpbf(rp[p]);
            s += f.x + f.y;
        }
        atomicAdd(&g_m[tid], s);
    }
}

// ---------------- gmkA: T = W'.S, diag norms, G (12 blocks) ------------------
__global__ __launch_bounds__(256, 1) void gmkA() {
    extern __shared__ float fs[];
    float* S_s = fs;                          // 36864
    float* T_s = fs + 36864;                  // 6144
    unsigned* Wa = (unsigned*)(T_s + 6144);   // 3072: primary (A or B) bf16x2
    unsigned* Wc = Wa + 3072;                 // 3072: secondary (B) for side 0
    float* m_s = (float*)(Wc + 3072);         // 192
    float* red = m_s + 192;                   // 256
    const int tid = threadIdx.x;
    const int h = blockIdx.x >> 1, side = blockIdx.x & 1;

    // load S with tile-level mirror
    for (int idx = tid; idx < 36864; idx += 256) {
        int a = idx / 192, b = idx - a * 192;
        int src = ((a >> 5) <= (b >> 5)) ? idx : b * 192 + a;
        S_s[idx] = g_S[src];
    }
    {
        const float* WA = g_wcomp + side * 36864 + h * 32 * 192;
        for (int i = tid; i < 3072; i += 256) {
            int d = i / 96, cp = i - d * 96;
            Wa[i] = packbf(WA[d * 192 + 2 * cp], WA[d * 192 + 2 * cp + 1]);
        }
        if (side == 0) {
            const float* WB = g_wcomp + 36864 + h * 32 * 192;
            for (int i = tid; i < 3072; i += 256) {
                int d = i / 96, cp = i - d * 96;
                Wc[i] = packbf(WB[d * 192 + 2 * cp], WB[d * 192 + 2 * cp + 1]);
            }
        }
    }
    for (int i = tid; i < 192; i += 256) m_s[i] = g_m[i];
    __syncthreads();

    // T[d][c0..c0+23] = sum_c' W[d][c'] S[c'][c];  mdot = W[d].m
    const int d = tid >> 3, j = tid & 7, c0 = j * 24;
    float t[24];
#pragma unroll
    for (int i = 0; i < 24; i++) t[i] = 0.f;
    float mdot = 0.f;
    for (int cp = 0; cp < 96; cp++) {
        float2 af = unpbf(Wa[d * 96 + cp]);
        const float* r0 = S_s + (2 * cp) * 192 + c0;
        const float* r1 = r0 + 192;
#pragma unroll
        for (int i = 0; i < 24; i++) t[i] += af.x * r0[i] + af.y * r1[i];
        mdot += af.x * m_s[2 * cp] + af.y * m_s[2 * cp + 1];
    }
    // diag partial: sum t[i] * W[d][c0+i]
    float dp = 0.f;
#pragma unroll
    for (int i = 0; i < 24; i += 2) {
        float2 af = unpbf(Wa[d * 96 + (c0 + i) / 2]);
        dp += t[i] * af.x + t[i + 1] * af.y;
    }
    if (side == 0) {
#pragma unroll
        for (int i = 0; i < 24; i++) T_s[d * 192 + c0 + i] = t[i];
    }
    red[tid] = dp;
    if (j == 0) {
        if (side == 0) g_Am[h * 32 + d] = mdot;
        else           g_Bm[h * 32 + d] = mdot;
    }
    __syncthreads();
    if (tid < 32) {
        float s = 0.f;
#pragma unroll
        for (int jj = 0; jj < 8; jj++) s += red[tid * 8 + jj];
        if (side == 0) g_qsA[h * 32 + tid] = s;
        else           g_ksB[h * 32 + tid] = s;
    }
    if (side == 0) {
        // G[dd][e] = T[dd] . B[e]
#pragma unroll
        for (int k = 0; k < 4; k++) {
            int p = tid + k * 256;
            int dd = p >> 5, e = p & 31;
            const float* Trow = T_s + dd * 192;
            float s = 0.f;
#pragma unroll 4
            for (int cp = 0; cp < 96; cp++) {
                float2 bf = unpbf(Wc[e * 96 + cp]);
                s += Trow[2 * cp] * bf.x + Trow[2 * cp + 1] * bf.y;
            }
            g_Gt[h * 1024 + p] = s;
        }
    }
}

// ---------------- gmkB: finalize attn + mn mix + gating (6 blocks) -----------
__global__ void gmkB(const float* __restrict__ mn_w,
                     const float* __restrict__ gating) {
    __shared__ float Gt[1024], attn[1024], mn_t[2048];
    __shared__ float rq[32], rk[32], Amv[32], Bmv[32], bqv[32], bkv[32];
    const int tid = threadIdx.x, h = blockIdx.x;
    for (int i = tid; i < 1024; i += 256) Gt[i] = g_Gt[h * 1024 + i];
    for (int i = tid; i < 2048; i += 256) mn_t[(i & 31) * 64 + (i >> 5)] = mn_w[i];
    if (tid < 32) {
        float bq = g_bcomp[h * 32 + tid], bk = g_bcomp[192 + h * 32 + tid];
        float am = g_Am[h * 32 + tid],  bm = g_Bm[h * 32 + tid];
        bqv[tid] = bq; bkv[tid] = bk; Amv[tid] = am; Bmv[tid] = bm;
        float qs2 = g_qsA[h * 32 + tid] + 2.f * bq * am + (float)HW * bq * bq;
        rq[tid] = 1.f / fmaxf(sqrtf(qs2), 1e-12f);
        float ks2 = g_ksB[h * 32 + tid] + 2.f * bk * bm + (float)HW * bk * bk;
        rk[tid] = 1.f / fmaxf(sqrtf(ks2), 1e-12f);
    }
    __syncthreads();
#pragma unroll
    for (int k = 0; k < 4; k++) {
        int p = tid + k * 256;
        int dd = p >> 5, e = p & 31;
        float G = Gt[p] + Amv[dd] * bkv[e] + bqv[dd] * Bmv[e]
                + (float)HW * bqv[dd] * bkv[e];
        attn[p] = G * rq[dd] * rk[e];
    }
    __syncthreads();
    float g1 = __ldg(&gating[h]), g2 = __ldg(&gating[NH + h]);
#pragma unroll
    for (int k = 0; k < 2; k++) {
        int p = tid + k * 256;
        int dd = p >> 4, j = p & 15, e2 = 2 * j;
        float s1a = 0.f, s1b = 0.f, s2a = 0.f, s2b = 0.f;
#pragma unroll
        for (int e = 0; e < 32; e++) {
            float a = attn[dd * 32 + e];
            const float* mr = mn_t + e * 64;
            s1a += a * mr[e2];      s1b += a * mr[e2 + 1];
            s2a += a * mr[32 + e2]; s2b += a * mr[33 + e2];
        }
        g_gmbf[(h * 32 + dd) * 16 + j] = packbf(g1 * s1a + g2 * s2a,
                                                g1 * s1b + g2 * s2b);
    }
}

// ---------------- k4: mi(mma) + t=mi*v + softmax + proj + residual -----------
__global__ __launch_bounds__(256, 2) void k4(const float* __restrict__ cond,
                                             const float* __restrict__ x,
                                             float* __restrict__ out) {
    extern __shared__ unsigned sm[];
    unsigned* c_s  = sm;                 // 12800 u32: cond -> t(bf16) -> softmax
    unsigned* w_s  = sm + 12800;         // 6400 (double buffer)
    unsigned* gm_s = sm + 12800 + 6400;  // 192*20
    const int tid = threadIdx.x, lane = tid & 31, warp = tid >> 5;
    const int gid = lane >> 2, tg = lane & 3;
    const int mb = (warp & 1) * 64, nb = (warp >> 1) * 48;
    const int p0 = blockIdx.x * TPB;

    for (int i = tid; i < C * 16; i += 256) gm_s[(i >> 4) * 20 + (i & 15)] = g_gmbf[i];
    for (int c2 = warp; c2 < 96; c2 += 8) {
        int c = 2 * c2;
#pragma unroll
        for (int pb = 0; pb < TPB; pb += 32) {
            float v0 = cond[(size_t)c * HW + p0 + pb + lane];
            float v1 = cond[(size_t)(c + 1) * HW + p0 + pb + lane];
            c_s[(pb + lane) * PXS + c2] = packbf(v0, v1);
        }
    }
    __syncthreads();

    float acc[4][6][4];
#pragma unroll
    for (int mt = 0; mt < 4; mt++)
#pragma unroll
        for (int nt = 0; nt < 6; nt++)
#pragma unroll
            for (int r = 0; r < 4; r++) acc[mt][nt][r] = 0.f;
#pragma unroll
    for (int kl = 0; kl < 2; kl++) {
        const int k2 = kl * 8;
        int hprev = -1;
        unsigned a[4][4];
#pragma unroll
        for (int nt = 0; nt < 6; nt++) {
            int h = (nb + nt * 8) >> 5;
            if (h != hprev) {
#pragma unroll
                for (int mt = 0; mt < 4; mt++) {
                    const unsigned* ab = c_s + (mb + mt * 16 + gid) * PXS + h * 16 + k2 + tg;
                    a[mt][0] = ab[0];
                    a[mt][1] = ab[8 * PXS];
                    a[mt][2] = ab[4];
                    a[mt][3] = ab[8 * PXS + 4];
                }
                hprev = h;
            }
            const unsigned* gp = gm_s + (nb + nt * 8 + gid) * 20 + k2 + tg;
            unsigned b0 = gp[0], b1 = gp[4];
#pragma unroll
            for (int mt = 0; mt < 4; mt++) mma_bf16(acc[mt][nt], a[mt], b0, b1);
        }
    }
    __syncthreads();

    // t = mi * v  (bf16x2 in place over c_s)
#pragma unroll
    for (int mt = 0; mt < 4; mt++)
#pragma unroll
        for (int nt = 0; nt < 6; nt++) {
            int px = mb + mt * 16 + gid, cp = (nb + nt * 8) / 2 + tg;
            float2 v0 = unpbf(__ldg(&g_v[(size_t)(p0 + px) * 96 + cp]));
            float2 v1 = unpbf(__ldg(&g_v[(size_t)(p0 + px + 8) * 96 + cp]));
            c_s[px * PXS + cp]       = packbf(acc[mt][nt][0] * v0.x, acc[mt][nt][1] * v0.y);
            c_s[(px + 8) * PXS + cp] = packbf(acc[mt][nt][2] * v1.x, acc[mt][nt][3] * v1.y);
        }
    __syncthreads();

    // softmax over head-dim per (px, head), in place
#pragma unroll
    for (int k = 0; k < 3; k++) {
        int task = tid + k * 256;
        int px = task & 127, h = task >> 7;
        unsigned* row = c_s + px * PXS + h * 16;
        float e[32];
        float m = -1e30f;
#pragma unroll
        for (int j = 0; j < 16; j++) {
            float2 f = unpbf(row[j]);
            e[2 * j] = f.x; e[2 * j + 1] = f.y;
            m = fmaxf(m, fmaxf(f.x, f.y));
        }
        float s = 0.f;
#pragma unroll
        for (int d = 0; d < 32; d++) {
            e[d] = __expf(e[d] - m);
            s += e[d];
        }
        float r = 1.f / s;
#pragma unroll
        for (int j = 0; j < 16; j++) row[j] = packbf(e[2 * j] * r, e[2 * j + 1] * r);
    }

    // proj GEMM + residual
#pragma unroll
    for (int mt = 0; mt < 4; mt++)
#pragma unroll
        for (int nt = 0; nt < 6; nt++)
#pragma unroll
            for (int r = 0; r < 4; r++) acc[mt][nt][r] = 0.f;
    gemm_db128(c_s, w_s, g_wbf + MS, acc, tid);
#pragma unroll
    for (int mt = 0; mt < 4; mt++)
#pragma unroll
        for (int nt = 0; nt < 6; nt++) {
            int o = nb + nt * 8 + 2 * tg;
            size_t i00 = (size_t)o * HW + p0 + mb + mt * 16 + gid;
            out[i00]          = acc[mt][nt][0] + __ldg(&x[i00]);
            out[i00 + HW]     = acc[mt][nt][1] + __ldg(&x[i00 + HW]);
            out[i00 + 8]      = acc[mt][nt][2] + __ldg(&x[i00 + 8]);
            out[i00 + HW + 8] = acc[mt][nt][3] + __ldg(&x[i00 + HW + 8]);
        }
}

// ---------------- launch -----------------------------------------------------
extern "C" void kernel_launch(void* const* d_in, const int* in_sizes, int n_in,
                              void* d_out, int out_size) {
    const float* x      = (const float*)d_in[0];
    const float* cond   = (const float*)d_in[1];
    const float* ln_g   = (const float*)d_in[2];
    const float* ln_b   = (const float*)d_in[3];
    const float* qkv_w  = (const float*)d_in[6];
    const float* pre_w  = (const float*)d_in[4];
    const float* pre_b  = (const float*)d_in[5];
    const float* mn_w   = (const float*)d_in[7];
    const float* gating = (const float*)d_in[8];
    const float* proj_w = (const float*)d_in[9];
    float* out = (float*)d_out;

    const int SM12 = 20224 * 4;   // 80896 B
    const int SMA  = 49600 * 4;   // 198400 B
    const int SM4  = (12800 + 2 * WBUF + 192 * 20) * 4;  // 92160 B
    cudaFuncSetAttribute(k12,  cudaFuncAttributeMaxDynamicSharedMemorySize, SM12);
    cudaFuncSetAttribute(gmkA, cudaFuncAttributeMaxDynamicSharedMemorySize, SMA);
    cudaFuncSetAttribute(k4,   cudaFuncAttributeMaxDynamicSharedMemorySize, SM4);

    prep_compose<<<435, 256>>>(qkv_w, pre_w, pre_b);
    prep_pack<<<289, 256>>>(proj_w);
    k12<<<HW / TPA, 256, SM12>>>(x, ln_g, ln_b);
    gmkA<<<12, 256, SMA>>>();
    gmkB<<<6, 256>>>(mn_w, gating);
    k4<<<HW / TPB, 256, SM4>>>(cond, x, out);
}

// round 11
// speedup vs baseline: 1.1017x; 1.1017x over previous
#include <cuda_runtime.h>
#include <cuda_bf16.h>

#define HW 200704
#define C 192
#define NH 6
#define D 32
#define PXS 100    // u32 stride for px-major bf16x2 tiles
#define WST 200    // u32 stride per k-pair row in weight chunk
#define WBUF 3200  // u32 per weight chunk buffer
#define MS  (96 * 192)   // u32 per packed weight matrix

#define TPA 64     // k12 tile px
#define QSA 72     // bf16 stride for ch-major q/k tiles
#define TPB 128    // k4 tile px

// ---------------- scratch ----------------------------------------------------
__device__ float    g_wcomp[3 * 36864];   // composed fp32 Wq',Wk',Wv'
__device__ float    g_bcomp[3 * 192];     // composed biases bq,bk,bv
__device__ unsigned g_wbf[4 * MS];        // bf16x2 [cp][o]: Wq',Wk',Wv',proj
__device__ unsigned g_v[(size_t)HW * 96]; // v, px-major bf16x2 (global px)
__device__ float    g_G[NH * D * D];
__device__ float    g_qs2[C];
__device__ float    g_ks2[C];
__device__ unsigned g_gmbf[C * 16];       // gm bf16x2 pairs [ch][e/2]

// ---------------- helpers ----------------------------------------------------
__device__ __forceinline__ unsigned packbf(float a, float b) {
    __nv_bfloat162 p = __floats2bfloat162_rn(a, b);
    return *(unsigned*)&p;
}
__device__ __forceinline__ float2 unpbf(unsigned u) {
    __nv_bfloat162 p = *(__nv_bfloat162*)&u;
    return __bfloat1622float2(p);
}
__device__ __forceinline__ void mma_bf16(float d[4], const unsigned a[4],
                                         unsigned b0, unsigned b1) {
    asm volatile(
        "mma.sync.aligned.m16n8k16.row.col.f32.bf16.bf16.f32 "
        "{%0,%1,%2,%3},{%4,%5,%6,%7},{%8,%9},{%0,%1,%2,%3};\n"
        : "+f"(d[0]), "+f"(d[1]), "+f"(d[2]), "+f"(d[3])
        : "r"(a[0]), "r"(a[1]), "r"(a[2]), "r"(a[3]), "r"(b0), "r"(b1));
}

__device__ __forceinline__ void wchunk_prefetch(unsigned* wbuf,
                                                const unsigned* __restrict__ wg,
                                                int ch, int tid) {
#pragma unroll
    for (int r = 0; r < 3; r++) {
        int seg = tid + r * 256;
        int j = seg / 48, off = (seg - j * 48) * 4;
        unsigned ds = (unsigned)__cvta_generic_to_shared(wbuf + j * WST + off);
        asm volatile("cp.async.cg.shared.global [%0], [%1], 16;"
                     :: "r"(ds), "l"(wg + ch * 3072 + j * 192 + off));
    }
    asm volatile("cp.async.commit_group;" ::: "memory");
}

// 64px-tile GEMM, warp grid 2Mx4N (warp tile 32px x 48ch)
__device__ __forceinline__ void gemm_db64(const unsigned* a_s, unsigned* w_s,
                                          const unsigned* __restrict__ wg,
                                          float acc[2][6][4], int tid) {
    const int lane = tid & 31, warp = tid >> 5;
    const int gid = lane >> 2, tg = lane & 3;
    const int mb = (warp & 1) * 32, nb = (warp >> 1) * 48;
    wchunk_prefetch(w_s, wg, 0, tid);
    for (int ch = 0; ch < 6; ch++) {
        asm volatile("cp.async.wait_group 0;" ::: "memory");
        __syncthreads();
        if (ch < 5) wchunk_prefetch(w_s + ((ch + 1) & 1) * WBUF, wg, ch + 1, tid);
        const unsigned* wb_base = w_s + (ch & 1) * WBUF;
#pragma unroll
        for (int kl = 0; kl < 2; kl++) {
            const int k2 = ch * 16 + kl * 8;
            unsigned a[2][4];
#pragma unroll
            for (int mt = 0; mt < 2; mt++) {
                const unsigned* ab = a_s + (mb + mt * 16 + gid) * PXS + k2 + tg;
                a[mt][0] = ab[0];
                a[mt][1] = ab[8 * PXS];
                a[mt][2] = ab[4];
                a[mt][3] = ab[8 * PXS + 4];
            }
#pragma unroll
            for (int nt = 0; nt < 6; nt++) {
                const unsigned* wb = wb_base + (kl * 8 + tg) * WST + nb + nt * 8 + gid;
                unsigned b0 = wb[0], b1 = wb[4 * WST];
#pragma unroll
                for (int mt = 0; mt < 2; mt++) mma_bf16(acc[mt][nt], a[mt], b0, b1);
            }
        }
    }
}

// 128px-tile GEMM, warp grid 2Mx4N (warp tile 64px x 48ch)
__device__ __forceinline__ void gemm_db128(const unsigned* a_s, unsigned* w_s,
                                           const unsigned* __restrict__ wg,
                                           float acc[4][6][4], int tid) {
    const int lane = tid & 31, warp = tid >> 5;
    const int gid = lane >> 2, tg = lane & 3;
    const int mb = (warp & 1) * 64, nb = (warp >> 1) * 48;
    wchunk_prefetch(w_s, wg, 0, tid);
    for (int ch = 0; ch < 6; ch++) {
        asm volatile("cp.async.wait_group 0;" ::: "memory");
        __syncthreads();
        if (ch < 5) wchunk_prefetch(w_s + ((ch + 1) & 1) * WBUF, wg, ch + 1, tid);
        const unsigned* wb_base = w_s + (ch & 1) * WBUF;
#pragma unroll
        for (int kl = 0; kl < 2; kl++) {
            const int k2 = ch * 16 + kl * 8;
            unsigned a[4][4];
#pragma unroll
            for (int mt = 0; mt < 4; mt++) {
                const unsigned* ab = a_s + (mb + mt * 16 + gid) * PXS + k2 + tg;
                a[mt][0] = ab[0];
                a[mt][1] = ab[8 * PXS];
                a[mt][2] = ab[4];
                a[mt][3] = ab[8 * PXS + 4];
            }
#pragma unroll
            for (int nt = 0; nt < 6; nt++) {
                const unsigned* wb = wb_base + (kl * 8 + tg) * WST + nb + nt * 8 + gid;
                unsigned b0 = wb[0], b1 = wb[4 * WST];
#pragma unroll
                for (int mt = 0; mt < 4; mt++) mma_bf16(acc[mt][nt], a[mt], b0, b1);
            }
        }
    }
}

// ---------------- prep_compose: W' = Wsel * W_pre, b' = Wsel * pre_b ---------
__global__ void prep_compose(const float* __restrict__ qkv_w,
                             const float* __restrict__ pre_w,
                             const float* __restrict__ pre_b) {
    int idx = blockIdx.x * 256 + threadIdx.x;
    if (idx < 110592) {
        int sel = idx / 36864, r = idx - sel * 36864;
        int o = r / 192, c = r - o * 192;
        const float* wr = qkv_w + (sel * 192 + o) * 192;
        float s = 0.f;
#pragma unroll 4
        for (int i = 0; i < 192; i++) s += __ldg(&wr[i]) * __ldg(&pre_w[i * 192 + c]);
        g_wcomp[idx] = s;
    } else if (idx < 111168) {
        int b = idx - 110592;
        int sel = b / 192, o = b - sel * 192;
        const float* wr = qkv_w + (sel * 192 + o) * 192;
        float s = 0.f;
        for (int i = 0; i < 192; i++) s += __ldg(&wr[i]) * __ldg(&pre_b[i]);
        g_bcomp[b] = s;
    }
}

// ---------------- prep_pack: pack W'q/W'k/W'v + proj to bf16x2, zero accum ---
__global__ void prep_pack(const float* __restrict__ proj_w) {
    int idx = blockIdx.x * 256 + threadIdx.x;
    if (idx < 4 * MS) {
        int m = idx / MS, r = idx - m * MS;
        int cp = r / 192, o = r - cp * 192;
        const float* W = (m < 3) ? (g_wcomp + m * 36864) : proj_w;
        g_wbf[idx] = packbf(W[o * 192 + 2 * cp], W[o * 192 + 2 * cp + 1]);
    }
    if (blockIdx.x == 0) {
        for (int i = threadIdx.x; i < NH * D * D; i += 256) g_G[i] = 0.f;
        if (threadIdx.x < C) {
            g_qs2[threadIdx.x] = 0.f;
            g_ks2[threadIdx.x] = 0.f;
        }
    }
}

// ---------------- k12: LN + q/k/v GEMMs (composed) + Gram (2 CTA/SM) ---------
__global__ __launch_bounds__(256, 2) void k12(const float* __restrict__ x,
                                              const float* __restrict__ lng,
                                              const float* __restrict__ lnb) {
    extern __shared__ unsigned sm[];
    unsigned* bufA = sm;                      // 6400: xn px-major (stays live)
    unsigned* qbuf = sm + 6400;               // 6912: q_s ch-major bf16
    unsigned* kbuf = sm + 6400 + 6912;        // 6912: k_s ch-major bf16
    unsigned* w_s  = sm + 6400 + 2 * 6912;    // 6400: weight double buffer
    float* gb = (float*)(w_s + 2 * WBUF);     // g[192], b[192]
    float* mu = gb + 384;                     // 64
    float* rs = mu + 64;                      // 64
    const int tid = threadIdx.x, lane = tid & 31, warp = tid >> 5;
    const int gid = lane >> 2, tg = lane & 3;
    const int mb = (warp & 1) * 32, nb = (warp >> 1) * 48;
    const int p0 = blockIdx.x * TPA;

    for (int i = tid; i < C; i += 256) {
        gb[i]       = lng[i];
        gb[192 + i] = lnb[i];
    }
    // x transpose into px-major bf16x2
    for (int c2 = warp; c2 < 96; c2 += 8) {
        int c = 2 * c2;
#pragma unroll
        for (int pb = 0; pb < TPA; pb += 32) {
            float v0 = x[(size_t)c * HW + p0 + pb + lane];
            float v1 = x[(size_t)(c + 1) * HW + p0 + pb + lane];
            bufA[(pb + lane) * PXS + c2] = packbf(v0, v1);
        }
    }
    __syncthreads();
    // LN stats
    for (int px = warp; px < TPA; px += 8) {
        float s = 0.f, s2 = 0.f;
        for (int c2 = lane; c2 < 96; c2 += 32) {
            float2 f = unpbf(bufA[px * PXS + c2]);
            s += f.x + f.y;
            s2 += f.x * f.x + f.y * f.y;
        }
#pragma unroll
        for (int o = 16; o; o >>= 1) {
            s  += __shfl_xor_sync(~0u, s, o);
            s2 += __shfl_xor_sync(~0u, s2, o);
        }
        if (lane == 0) {
            float m = s * (1.f / C), v = s2 * (1.f / C) - m * m;
            mu[px] = m;
            rs[px] = rsqrtf(v + 1e-5f);
        }
    }
    __syncthreads();
    // apply LN in place
    for (int px = warp; px < TPA; px += 8) {
        float m = mu[px], r = rs[px];
        for (int c2 = lane; c2 < 96; c2 += 32) {
            float2 f = unpbf(bufA[px * PXS + c2]);
            f.x = (f.x - m) * r * gb[2 * c2]     + gb[192 + 2 * c2];
            f.y = (f.y - m) * r * gb[2 * c2 + 1] + gb[192 + 2 * c2 + 1];
            bufA[px * PXS + c2] = packbf(f.x, f.y);
        }
    }

    float acc[2][6][4];
    // ---- q GEMM (composed bias bq) -> q_s ch-major ----
#pragma unroll
    for (int nt = 0; nt < 6; nt++) {
        int o = nb + nt * 8 + 2 * tg;
        float b0 = __ldg(&g_bcomp[o]), b1 = __ldg(&g_bcomp[o + 1]);
#pragma unroll
        for (int mt = 0; mt < 2; mt++) {
            acc[mt][nt][0] = b0; acc[mt][nt][1] = b1;
            acc[mt][nt][2] = b0; acc[mt][nt][3] = b1;
        }
    }
    gemm_db64(bufA, w_s, g_wbf, acc, tid);
    {
        __nv_bfloat16* q_s = (__nv_bfloat16*)qbuf;
#pragma unroll
        for (int mt = 0; mt < 2; mt++)
#pragma unroll
            for (int nt = 0; nt < 6; nt++) {
                int o = nb + nt * 8 + 2 * tg, p = mb + mt * 16 + gid;
                q_s[o * QSA + p]           = __float2bfloat16(acc[mt][nt][0]);
                q_s[(o + 1) * QSA + p]     = __float2bfloat16(acc[mt][nt][1]);
                q_s[o * QSA + p + 8]       = __float2bfloat16(acc[mt][nt][2]);
                q_s[(o + 1) * QSA + p + 8] = __float2bfloat16(acc[mt][nt][3]);
            }
    }
    // ---- k GEMM (composed bias bk) -> k_s ch-major ----
#pragma unroll
    for (int nt = 0; nt < 6; nt++) {
        int o = nb + nt * 8 + 2 * tg;
        float b0 = __ldg(&g_bcomp[192 + o]), b1 = __ldg(&g_bcomp[192 + o + 1]);
#pragma unroll
        for (int mt = 0; mt < 2; mt++) {
            acc[mt][nt][0] = b0; acc[mt][nt][1] = b1;
            acc[mt][nt][2] = b0; acc[mt][nt][3] = b1;
        }
    }
    gemm_db64(bufA, w_s, g_wbf + MS, acc, tid);
    {
        __nv_bfloat16* k_s = (__nv_bfloat16*)kbuf;
#pragma unroll
        for (int mt = 0; mt < 2; mt++)
#pragma unroll
            for (int nt = 0; nt < 6; nt++) {
                int o = nb + nt * 8 + 2 * tg, p = mb + mt * 16 + gid;
                k_s[o * QSA + p]           = __float2bfloat16(acc[mt][nt][0]);
                k_s[(o + 1) * QSA + p]     = __float2bfloat16(acc[mt][nt][1]);
                k_s[o * QSA + p + 8]       = __float2bfloat16(acc[mt][nt][2]);
                k_s[(o + 1) * QSA + p + 8] = __float2bfloat16(acc[mt][nt][3]);
            }
    }
    // ---- v GEMM (composed bias bv) -> DRAM bf16x2 px-major ----
#pragma unroll
    for (int nt = 0; nt < 6; nt++) {
        int o = nb + nt * 8 + 2 * tg;
        float b0 = __ldg(&g_bcomp[384 + o]), b1 = __ldg(&g_bcomp[384 + o + 1]);
#pragma unroll
        for (int mt = 0; mt < 2; mt++) {
            acc[mt][nt][0] = b0; acc[mt][nt][1] = b1;
            acc[mt][nt][2] = b0; acc[mt][nt][3] = b1;
        }
    }
    gemm_db64(bufA, w_s, g_wbf + 2 * MS, acc, tid);
#pragma unroll
    for (int mt = 0; mt < 2; mt++)
#pragma unroll
        for (int nt = 0; nt < 6; nt++) {
            int px = mb + mt * 16 + gid, cp = (nb + nt * 8) / 2 + tg;
            g_v[(size_t)(p0 + px) * 96 + cp]     = packbf(acc[mt][nt][0], acc[mt][nt][1]);
            g_v[(size_t)(p0 + px + 8) * 96 + cp] = packbf(acc[mt][nt][2], acc[mt][nt][3]);
        }
    __syncthreads();

    // ---- Gram per head via bf16 mma over 64 px (warp w == head w) -----------
    if (warp < 6) {
        const __nv_bfloat16* q_s = (const __nv_bfloat16*)qbuf;
        const __nv_bfloat16* k_s = (const __nv_bfloat16*)kbuf;
        const int h = warp;
        float dG[2][4][4];
#pragma unroll
        for (int mt = 0; mt < 2; mt++)
#pragma unroll
            for (int nt = 0; nt < 4; nt++)
#pragma unroll
                for (int r = 0; r < 4; r++) dG[mt][nt][r] = 0.f;
#pragma unroll
        for (int kc = 0; kc < TPA; kc += 16) {
            unsigned a[2][4];
#pragma unroll
            for (int mt = 0; mt < 2; mt++) {
                const __nv_bfloat16* ab = q_s + (h * 32 + mt * 16 + gid) * QSA + kc + 2 * tg;
                a[mt][0] = *(const unsigned*)(ab);
                a[mt][1] = *(const unsigned*)(ab + 8 * QSA);
                a[mt][2] = *(const unsigned*)(ab + 8);
                a[mt][3] = *(const unsigned*)(ab + 8 * QSA + 8);
            }
#pragma unroll
            for (int nt = 0; nt < 4; nt++) {
                const __nv_bfloat16* bb = k_s + (h * 32 + nt * 8 + gid) * QSA + kc + 2 * tg;
                unsigned b0 = *(const unsigned*)(bb);
                unsigned b1 = *(const unsigned*)(bb + 8);
#pragma unroll
                for (int mt = 0; mt < 2; mt++) mma_bf16(dG[mt][nt], a[mt], b0, b1);
            }
        }
#pragma unroll
        for (int mt = 0; mt < 2; mt++)
#pragma unroll
            for (int nt = 0; nt < 4; nt++) {
                int r0 = h * 32 + mt * 16 + gid, c0 = nt * 8 + 2 * tg;
                atomicAdd(&g_G[r0 * 32 + c0],           dG[mt][nt][0]);
                atomicAdd(&g_G[r0 * 32 + c0 + 1],       dG[mt][nt][1]);
                atomicAdd(&g_G[(r0 + 8) * 32 + c0],     dG[mt][nt][2]);
                atomicAdd(&g_G[(r0 + 8) * 32 + c0 + 1], dG[mt][nt][3]);
            }
    }
    // squared norms from the same bf16 values
    for (int i = tid; i < 2 * C; i += 256) {
        const unsigned* arr = (i < C) ? qbuf : kbuf;
        int row = (i < C) ? i : i - C;
        const unsigned* rp = arr + row * (QSA / 2);
        float s = 0.f;
#pragma unroll
        for (int p = 0; p < TPA / 2; p++) {
            float2 f = unpbf(rp[p]);
            s += f.x * f.x + f.y * f.y;
        }
        atomicAdd((i < C) ? &g_qs2[row] : &g_ks2[row], s);
    }
}

// ---------------- gmk: attn normalize + mn mix + gating (12 blocks) ----------
__global__ void gmk_kernel(const float* __restrict__ mn_w,
                           const float* __restrict__ gating) {
    __shared__ float mn_t[32 * 64];  // [e][o]
    __shared__ float rk_s[32];
    const int tid = threadIdx.x;
    const int idx = blockIdx.x * 256 + tid;  // pair index
    const int dd = idx >> 4, pr = idx & 15, h = dd >> 5;
    for (int i = tid; i < 2048; i += 256) mn_t[(i & 31) * 64 + (i >> 5)] = mn_w[i];
    if (tid < 32) rk_s[tid] = 1.f / fmaxf(sqrtf(g_ks2[h * 32 + tid]), 1e-12f);
    __syncthreads();
    float rq = 1.f / fmaxf(sqrtf(g_qs2[dd]), 1e-12f);
    float a[32];
#pragma unroll
    for (int e = 0; e < 32; e++) a[e] = g_G[dd * 32 + e] * rq * rk_s[e];
    float s1a = 0.f, s1b = 0.f, s2a = 0.f, s2b = 0.f;
#pragma unroll
    for (int e = 0; e < 32; e++) {
        const float* mr = mn_t + e * 64;
        s1a += a[e] * mr[2 * pr];
        s1b += a[e] * mr[2 * pr + 1];
        s2a += a[e] * mr[32 + 2 * pr];
        s2b += a[e] * mr[33 + 2 * pr];
    }
    float g1 = __ldg(&gating[h]), g2 = __ldg(&gating[NH + h]);
    g_gmbf[idx] = packbf(g1 * s1a + g2 * s2a, g1 * s1b + g2 * s2b);
}

// ---------------- k4: mi(mma) + t=mi*v + softmax + proj + residual -----------
__global__ __launch_bounds__(256, 2) void k4(const float* __restrict__ cond,
                                             const float* __restrict__ x,
                                             float* __restrict__ out) {
    extern __shared__ unsigned sm[];
    unsigned* c_s  = sm;                 // 12800: cond -> t(bf16) -> softmax
    unsigned* w_s  = sm + 12800;         // 6400 (double buffer)
    unsigned* gm_s = sm + 12800 + 6400;  // 192*20
    const int tid = threadIdx.x, lane = tid & 31, warp = tid >> 5;
    const int gid = lane >> 2, tg = lane & 3;
    const int mb = (warp & 1) * 64, nb = (warp >> 1) * 48;
    const int p0 = blockIdx.x * TPB;

    for (int i = tid; i < C * 16; i += 256) gm_s[(i >> 4) * 20 + (i & 15)] = g_gmbf[i];
    for (int c2 = warp; c2 < 96; c2 += 8) {
        int c = 2 * c2;
#pragma unroll
        for (int pb = 0; pb < TPB; pb += 32) {
            float v0 = cond[(size_t)c * HW + p0 + pb + lane];
            float v1 = cond[(size_t)(c + 1) * HW + p0 + pb + lane];
            c_s[(pb + lane) * PXS + c2] = packbf(v0, v1);
        }
    }
    __syncthreads();

    float acc[4][6][4];
#pragma unroll
    for (int mt = 0; mt < 4; mt++)
#pragma unroll
        for (int nt = 0; nt < 6; nt++)
#pragma unroll
            for (int r = 0; r < 4; r++) acc[mt][nt][r] = 0.f;
#pragma unroll
    for (int kl = 0; kl < 2; kl++) {
        const int k2 = kl * 8;
        int hprev = -1;
        unsigned a[4][4];
#pragma unroll
        for (int nt = 0; nt < 6; nt++) {
            int h = (nb + nt * 8) >> 5;
            if (h != hprev) {
#pragma unroll
                for (int mt = 0; mt < 4; mt++) {
                    const unsigned* ab = c_s + (mb + mt * 16 + gid) * PXS + h * 16 + k2 + tg;
                    a[mt][0] = ab[0];
                    a[mt][1] = ab[8 * PXS];
                    a[mt][2] = ab[4];
                    a[mt][3] = ab[8 * PXS + 4];
                }
                hprev = h;
            }
            const unsigned* gp = gm_s + (nb + nt * 8 + gid) * 20 + k2 + tg;
            unsigned b0 = gp[0], b1 = gp[4];
#pragma unroll
            for (int mt = 0; mt < 4; mt++) mma_bf16(acc[mt][nt], a[mt], b0, b1);
        }
    }
    __syncthreads();

    // t = mi * v  (bf16x2 in place over c_s)
#pragma unroll
    for (int mt = 0; mt < 4; mt++)
#pragma unroll
        for (int nt = 0; nt < 6; nt++) {
            int px = mb + mt * 16 + gid, cp = (nb + nt * 8) / 2 + tg;
            float2 v0 = unpbf(__ldg(&g_v[(size_t)(p0 + px) * 96 + cp]));
            float2 v1 = unpbf(__ldg(&g_v[(size_t)(p0 + px + 8) * 96 + cp]));
            c_s[px * PXS + cp]       = packbf(acc[mt][nt][0] * v0.x, acc[mt][nt][1] * v0.y);
            c_s[(px + 8) * PXS + cp] = packbf(acc[mt][nt][2] * v1.x, acc[mt][nt][3] * v1.y);
        }
    __syncthreads();

    // softmax over head-dim per (px, head), in place
#pragma unroll
    for (int k = 0; k < 3; k++) {
        int task = tid + k * 256;
        int px = task & 127, h = task >> 7;
        unsigned* row = c_s + px * PXS + h * 16;
        float e[32];
        float m = -1e30f;
#pragma unroll
        for (int j = 0; j < 16; j++) {
            float2 f = unpbf(row[j]);
            e[2 * j] = f.x; e[2 * j + 1] = f.y;
            m = fmaxf(m, fmaxf(f.x, f.y));
        }
        float s = 0.f;
#pragma unroll
        for (int d = 0; d < 32; d++) {
            e[d] = __expf(e[d] - m);
            s += e[d];
        }
        float r = 1.f / s;
#pragma unroll
        for (int j = 0; j < 16; j++) row[j] = packbf(e[2 * j] * r, e[2 * j + 1] * r);
    }

    // proj GEMM + residual
#pragma unroll
    for (int mt = 0; mt < 4; mt++)
#pragma unroll
        for (int nt = 0; nt < 6; nt++)
#pragma unroll
            for (int r = 0; r < 4; r++) acc[mt][nt][r] = 0.f;
    gemm_db128(c_s, w_s, g_wbf + 3 * MS, acc, tid);
#pragma unroll
    for (int mt = 0; mt < 4; mt++)
#pragma unroll
        for (int nt = 0; nt < 6; nt++) {
            int o = nb + nt * 8 + 2 * tg;
            size_t i00 = (size_t)o * HW + p0 + mb + mt * 16 + gid;
            out[i00]          = acc[mt][nt][0] + __ldg(&x[i00]);
            out[i00 + HW]     = acc[mt][nt][1] + __ldg(&x[i00 + HW]);
            out[i00 + 8]      = acc[mt][nt][2] + __ldg(&x[i00 + 8]);
            out[i00 + HW + 8] = acc[mt][nt][3] + __ldg(&x[i00 + HW + 8]);
        }
}

// ---------------- launch -----------------------------------------------------
extern "C" void kernel_launch(void* const* d_in, const int* in_sizes, int n_in,
                              void* d_out, int out_size) {
    const float* x      = (const float*)d_in[0];
    const float* cond   = (const float*)d_in[1];
    const float* ln_g   = (const float*)d_in[2];
    const float* ln_b   = (const float*)d_in[3];
    const float* pre_w  = (const float*)d_in[4];
    const float* pre_b  = (const float*)d_in[5];
    const float* qkv_w  = (const float*)d_in[6];
    const float* mn_w   = (const float*)d_in[7];
    const float* gating = (const float*)d_in[8];
    const float* proj_w = (const float*)d_in[9];
    float* out = (float*)d_out;

    const int SM12 = (6400 + 2 * 6912 + 2 * WBUF + 512) * 4;  // 108544 B
    const int SM4  = (12800 + 2 * WBUF + 192 * 20) * 4;       // 92160 B
    cudaFuncSetAttribute(k12, cudaFuncAttributeMaxDynamicSharedMemorySize, SM12);
    cudaFuncSetAttribute(k4,  cudaFuncAttributeMaxDynamicSharedMemorySize, SM4);

    prep_compose<<<435, 256>>>(qkv_w, pre_w, pre_b);
    prep_pack<<<(4 * MS + 255) / 256, 256>>>(proj_w);
    k12<<<HW / TPA, 256, SM12>>>(x, ln_g, ln_b);
    gmk_kernel<<<12, 256>>>(mn_w, gating);
    k4<<<HW / TPB, 256, SM4>>>(cond, x, out);
}